// round 1
// baseline (speedup 1.0000x reference)
#include <cuda_runtime.h>
#include <cstdint>

#define C 81

// Precomputed per-(center c, point q): geometric predicate bitmask over p,
// and the distance-based base weight. Board-independent.
__device__ ulonglong2 g_mask[C * C];
__device__ float      g_base[C * C];

// f32-rounded constants, matching JAX weak-typed scalar promotion:
// float32(180.0 / pi), float32(sqrt(2.0) * 9.0)
__device__ __forceinline__ float rad2deg_f32() { return (float)(180.0 / 3.14159265358979323846); }
__device__ __forceinline__ float maxdist_f32() { return (float)12.727922061357855; }

__global__ void precompute_kernel(const int* __restrict__ all_coords) {
    const int c   = blockIdx.x;
    const int tid = threadIdx.x;

    __shared__ int   sy[C], sx[C];
    __shared__ int   sd2[C];
    __shared__ float sang[C];

    if (tid < C) {
        sy[tid] = all_coords[tid * 3 + 1];
        sx[tid] = all_coords[tid * 3 + 2];
    }
    __syncthreads();

    const int cy = sy[c], cx = sx[c];

    if (tid < C) {
        int dy = sy[tid] - cy;
        int dx = sx[tid] - cx;
        sd2[tid] = dy * dy + dx * dx;
        // Replicate reference: raw = f32(atan2(-dy, dx)) * f32(180/pi);
        // angle = raw > 0 ? raw : raw + 360
        // (atan2 in double, rounded to f32 == correctly-rounded atan2f)
        float t   = (float)atan2(-(double)dy, (double)dx);
        float raw = __fmul_rn(t, rad2deg_f32());
        sang[tid] = (raw > 0.0f) ? raw : __fadd_rn(raw, 360.0f);
    }
    __syncthreads();

    if (tid < C) {
        const int   q   = tid;
        const float aq  = sang[q];
        const int   d2q = sd2[q];

        unsigned long long lo = 0ull, hi = 0ull;
        #pragma unroll 1
        for (int p = 0; p < C; p++) {
            // stable-argsort rank comparison, exact in integers
            int  d2p = sd2[p];
            bool rlt = (d2p < d2q) || (d2p == d2q && p < q);
            // wrapped angular difference, float32 exactly as reference
            float ad = fabsf(__fadd_rn(sang[p], -aq));
            if (ad > 180.0f) ad = __fadd_rn(360.0f, -ad);
            if (rlt && (ad < 45.0f)) {
                if (p < 64) lo |= 1ull << p;
                else        hi |= 1ull << (p - 64);
            }
        }
        g_mask[c * C + q] = make_ulonglong2(lo, hi);

        float dist = sqrtf((float)d2q);
        float base = __fdiv_rn(__fadd_rn(maxdist_f32(), -dist), maxdist_f32());
        if (base < 0.5f) base = __fmul_rn(base, 0.5f);
        g_base[c * C + q] = base;
    }
}

__global__ void influence_kernel(const float* __restrict__ board,
                                 float* __restrict__ out) {
    const int b   = blockIdx.x;
    const int tid = threadIdx.x;

    __shared__ int s[C];
    if (tid < C) s[tid] = (int)board[tid];  // exact: board in {-1,0,1}
    __syncthreads();

    if (s[b] != 0) {               // non-empty cell: output masked to 0
        if (tid == 0) out[b] = 0.0f;
        return;
    }

    // Hypothetical board: stone (+1) at b. Build sign bitmasks over p.
    unsigned long long posLo = 0, posHi = 0, negLo = 0, negHi = 0;
    #pragma unroll 1
    for (int p = 0; p < C; p++) {
        int v = (p == b) ? 1 : s[p];
        if (v > 0)      { if (p < 64) posLo |= 1ull << p; else posHi |= 1ull << (p - 64); }
        else if (v < 0) { if (p < 64) negLo |= 1ull << p; else negHi |= 1ull << (p - 64); }
    }

    float acc = 0.0f;
    for (int idx = tid; idx < C * C; idx += blockDim.x) {
        const int c = idx / C;
        const int q = idx - c * C;
        // center must be empty on the hypothetical board (c==b has a stone)
        if (c == b || s[c] != 0) continue;
        const int sq = (q == b) ? 1 : s[q];
        if (sq == 0) continue;

        ulonglong2 m = g_mask[idx];
        int k;
        if (sq > 0) k = __popcll(m.x & negLo) + __popcll(m.y & negHi);
        else        k = __popcll(m.x & posLo) + __popcll(m.y & posHi);

        // exp(k * log(0.5)) == 2^-k to ~1e-8 rel; k <= 81 so no underflow
        float w = __int_as_float((unsigned)(127 - k) << 23);
        acc += g_base[idx] * w * (float)sq;
    }

    // block reduction (128 threads = 4 warps)
    #pragma unroll
    for (int o = 16; o > 0; o >>= 1)
        acc += __shfl_down_sync(0xFFFFFFFFu, acc, o);

    __shared__ float wsum[4];
    if ((tid & 31) == 0) wsum[tid >> 5] = acc;
    __syncthreads();
    if (tid == 0) out[b] = (wsum[0] + wsum[1]) + (wsum[2] + wsum[3]);
}

extern "C" void kernel_launch(void* const* d_in, const int* in_sizes, int n_in,
                              void* d_out, int out_size) {
    // all_coords: 81x3 int32 (243 elems); board: 81 float32
    int ci = (in_sizes[0] == 3 * C) ? 0 : 1;
    int bi = 1 - ci;
    const int*   all_coords = (const int*)d_in[ci];
    const float* board      = (const float*)d_in[bi];
    float*       out        = (float*)d_out;

    precompute_kernel<<<C, 128>>>(all_coords);
    influence_kernel<<<C, 128>>>(board, out);
}

// round 4
// speedup vs baseline: 2.1130x; 2.1130x over previous
#include <cuda_runtime.h>
#include <cstdint>

#define C 81
#define CC (C * C)
#define NTHREADS 512
#define NITER 13  // ceil(6561 / 512)

// Packed per-(center c, point q):
//  .x           = mask bits p in [0,64)
//  .y bits[0:17)  = mask bits p in [64,81)
//  .y bits[32:64) = f32 bit pattern of the distance-based base weight
__device__ ulonglong2 g_pack[CC];

// f32-rounded constants, matching JAX weak-typed scalar promotion:
// float32(180.0 / pi), float32(sqrt(2.0) * 9.0)
__device__ __forceinline__ float rad2deg_f32() { return (float)(180.0 / 3.14159265358979323846); }
__device__ __forceinline__ float maxdist_f32() { return (float)12.727922061357855; }

__global__ void precompute_kernel(const int* __restrict__ all_coords) {
    const int c   = blockIdx.x;
    const int tid = threadIdx.x;

    __shared__ int   sy[C], sx[C];
    __shared__ int   sd2[C];
    __shared__ float sang[C];

    if (tid < C) {
        sy[tid] = all_coords[tid * 3 + 1];
        sx[tid] = all_coords[tid * 3 + 2];
    }
    __syncthreads();

    const int cy = sy[c], cx = sx[c];

    if (tid < C) {
        int dy = sy[tid] - cy;
        int dx = sx[tid] - cx;
        sd2[tid] = dy * dy + dx * dx;
        // Replicate reference bit-for-bit: raw = f32(atan2(-dy, dx)) * f32(180/pi);
        // angle = raw > 0 ? raw : raw + 360
        // (atan2 in double, rounded to f32 == correctly-rounded atan2f)
        float t   = (float)atan2(-(double)dy, (double)dx);
        float raw = __fmul_rn(t, rad2deg_f32());
        sang[tid] = (raw > 0.0f) ? raw : __fadd_rn(raw, 360.0f);
    }
    __syncthreads();

    if (tid < C) {
        const int   q   = tid;
        const float aq  = sang[q];
        const int   d2q = sd2[q];

        unsigned long long lo = 0ull, hi = 0ull;
        #pragma unroll
        for (int p = 0; p < C; p++) {
            // stable-argsort rank comparison, exact in integers
            int  d2p = sd2[p];
            bool rlt = (d2p < d2q) || (d2p == d2q && p < q);
            // wrapped angular difference, float32 exactly as reference
            float ad = fabsf(__fadd_rn(sang[p], -aq));
            if (ad > 180.0f) ad = __fadd_rn(360.0f, -ad);
            if (rlt && (ad < 45.0f)) {
                if (p < 64) lo |= 1ull << p;
                else        hi |= 1ull << (p - 64);
            }
        }

        float dist = sqrtf((float)d2q);
        float base = __fdiv_rn(__fadd_rn(maxdist_f32(), -dist), maxdist_f32());
        if (base < 0.5f) base = __fmul_rn(base, 0.5f);

        hi |= ((unsigned long long)__float_as_uint(base)) << 32;
        g_pack[c * C + q] = make_ulonglong2(lo, hi);
    }
}

__global__ __launch_bounds__(NTHREADS, 1)
void influence_kernel(const float* __restrict__ board,
                      float* __restrict__ out) {
    const int b   = blockIdx.x;
    const int tid = threadIdx.x;

    __shared__ int s[C];
    if (tid < C) s[tid] = (int)board[tid];  // exact: board values in {-1,0,1}
    __syncthreads();

    if (s[b] != 0) {               // non-empty cell: output masked to 0
        if (tid == 0) out[b] = 0.0f;
        return;
    }

    // Hypothetical board: stone (+1) at b. Build sign bitmasks over p.
    unsigned long long posLo = 0, posHi = 0, negLo = 0, negHi = 0;
    #pragma unroll
    for (int p = 0; p < C; p++) {
        int v = (p == b) ? 1 : s[p];
        if (v > 0)      { if (p < 64) posLo |= 1ull << p; else posHi |= 1ull << (p - 64); }
        else if (v < 0) { if (p < 64) negLo |= 1ull << p; else negHi |= 1ull << (p - 64); }
    }

    float acc = 0.0f;
    #pragma unroll
    for (int i = 0; i < NITER; i++) {
        const int idx = tid + i * NTHREADS;
        if (idx < CC) {
            const int c = idx / C;
            const int q = idx - c * C;
            // center must be empty on the hypothetical board (c==b has a stone)
            if (c != b && s[c] == 0) {
                const int sq = (q == b) ? 1 : s[q];
                if (sq != 0) {
                    ulonglong2 m = g_pack[idx];
                    unsigned long long hiMask = m.y;  // sign masks only use bits [0,17)
                    int k;
                    if (sq > 0) k = __popcll(m.x & negLo) + __popcll(hiMask & negHi);
                    else        k = __popcll(m.x & posLo) + __popcll(hiMask & posHi);

                    float base = __uint_as_float((unsigned)(m.y >> 32));
                    // exp(k * log(0.5)) == 2^-k to ~1e-8 rel; k <= 81 so no underflow
                    float w = __int_as_float((unsigned)(127 - k) << 23);
                    acc += base * w * (float)sq;
                }
            }
        }
    }

    // block reduction: 16 warps
    #pragma unroll
    for (int o = 16; o > 0; o >>= 1)
        acc += __shfl_down_sync(0xFFFFFFFFu, acc, o);

    __shared__ float wsum[NTHREADS / 32];
    if ((tid & 31) == 0) wsum[tid >> 5] = acc;
    __syncthreads();
    if (tid == 0) {
        float t = 0.0f;
        #pragma unroll
        for (int w = 0; w < NTHREADS / 32; w++) t += wsum[w];
        out[b] = t;
    }
}

extern "C" void kernel_launch(void* const* d_in, const int* in_sizes, int n_in,
                              void* d_out, int out_size) {
    // all_coords: 81x3 int32 (243 elems); board: 81 float32
    int ci = (in_sizes[0] == 3 * C) ? 0 : 1;
    int bi = 1 - ci;
    const int*   all_coords = (const int*)d_in[ci];
    const float* board      = (const float*)d_in[bi];
    float*       out        = (float*)d_out;

    precompute_kernel<<<C, 128>>>(all_coords);
    influence_kernel<<<C, NTHREADS>>>(board, out);
}

// round 5
// speedup vs baseline: 2.3720x; 1.1226x over previous
#include <cuda_runtime.h>
#include <cstdint>

#define C 81
#define CC (C * C)
#define NTHREADS 512

// Packed per-(center c, point q):
//  .x             = predicate mask bits p in [0,64)
//  .y bits[0:17)  = predicate mask bits p in [64,81)
//  .y bits[32:64) = f32 bit pattern of the distance-based base weight
__device__ ulonglong2 g_pack[CC];

// f32-rounded constants, matching JAX weak-typed scalar promotion:
// float32(180.0 / pi), float32(sqrt(2.0) * 9.0)
__device__ __forceinline__ float rad2deg_f32() { return (float)(180.0 / 3.14159265358979323846); }
__device__ __forceinline__ float maxdist_f32() { return (float)12.727922061357855; }

__global__ void precompute_kernel(const int* __restrict__ all_coords) {
    const int c   = blockIdx.x;
    const int tid = threadIdx.x;

    __shared__ int   sy[C], sx[C];
    __shared__ int   sd2[C];
    __shared__ float sang[C];

    if (tid < C) {
        sy[tid] = all_coords[tid * 3 + 1];
        sx[tid] = all_coords[tid * 3 + 2];
    }
    __syncthreads();

    const int cy = sy[c], cx = sx[c];

    if (tid < C) {
        int dy = sy[tid] - cy;
        int dx = sx[tid] - cx;
        sd2[tid] = dy * dy + dx * dx;
        // Replicate reference bit-for-bit: raw = f32(atan2(-dy, dx)) * f32(180/pi);
        // angle = raw > 0 ? raw : raw + 360
        // (atan2 in double, rounded to f32 == correctly-rounded atan2f)
        float t   = (float)atan2(-(double)dy, (double)dx);
        float raw = __fmul_rn(t, rad2deg_f32());
        sang[tid] = (raw > 0.0f) ? raw : __fadd_rn(raw, 360.0f);
    }
    __syncthreads();

    if (tid < C) {
        const int   q   = tid;
        const float aq  = sang[q];
        const int   d2q = sd2[q];

        unsigned long long lo = 0ull, hi = 0ull;
        #pragma unroll
        for (int p = 0; p < C; p++) {
            // stable-argsort rank comparison, exact in integers
            int  d2p = sd2[p];
            bool rlt = (d2p < d2q) || (d2p == d2q && p < q);
            // wrapped angular difference, float32 exactly as reference
            float ad = fabsf(__fadd_rn(sang[p], -aq));
            if (ad > 180.0f) ad = __fadd_rn(360.0f, -ad);
            if (rlt && (ad < 45.0f)) {
                if (p < 64) lo |= 1ull << p;
                else        hi |= 1ull << (p - 64);
            }
        }

        float dist = sqrtf((float)d2q);
        float base = __fdiv_rn(__fadd_rn(maxdist_f32(), -dist), maxdist_f32());
        if (base < 0.5f) base = __fmul_rn(base, 0.5f);

        hi |= ((unsigned long long)__float_as_uint(base)) << 32;
        g_pack[c * C + q] = make_ulonglong2(lo, hi);
    }

    // PDL: all results stored above; let the dependent grid launch.
    asm volatile("griddepcontrol.launch_dependents;" ::: "memory");
}

__global__ __launch_bounds__(NTHREADS, 1)
void influence_kernel(const float* __restrict__ board,
                      float* __restrict__ out) {
    const int b   = blockIdx.x;
    const int tid = threadIdx.x;

    __shared__ int s[C];
    __shared__ unsigned char ec[C];     // empty centers (c != b)
    __shared__ unsigned char qp[C];     // nonzero-q indices (incl. b as +1)
    __shared__ signed char   qsg[C];    // their signs
    __shared__ int ne_s, nq_s;
    __shared__ unsigned long long mshared[4];  // posLo, posHi, negLo, negHi

    if (tid < C) s[tid] = (int)board[tid];  // exact: board values in {-1,0,1}
    __syncthreads();

    if (s[b] != 0) {               // non-empty cell: output masked to 0 (uniform exit)
        if (tid == 0) out[b] = 0.0f;
        return;
    }

    // Warp 0 / thread 0: build compact lists (deterministic order).
    if (tid == 0) {
        int ne = 0, nq = 0;
        for (int p = 0; p < C; p++) {
            int v = (p == b) ? 1 : s[p];
            if (v == 0) ec[ne++] = (unsigned char)p;
            else { qp[nq] = (unsigned char)p; qsg[nq] = (signed char)v; nq++; }
        }
        ne_s = ne; nq_s = nq;
    }
    // Warp 1 / thread 32: build sign bitmasks over p (runs concurrently with warp 0).
    if (tid == 32) {
        unsigned long long posLo = 0, posHi = 0, negLo = 0, negHi = 0;
        for (int p = 0; p < C; p++) {
            int v = (p == b) ? 1 : s[p];
            if (v > 0)      { if (p < 64) posLo |= 1ull << p; else posHi |= 1ull << (p - 64); }
            else if (v < 0) { if (p < 64) negLo |= 1ull << p; else negHi |= 1ull << (p - 64); }
        }
        mshared[0] = posLo; mshared[1] = posHi;
        mshared[2] = negLo; mshared[3] = negHi;
    }
    __syncthreads();

    const int nq = nq_s;
    const int total = ne_s * nq;
    const unsigned long long posLo = mshared[0], posHi = mshared[1];
    const unsigned long long negLo = mshared[2], negHi = mshared[3];

    // PDL: g_pack produced by precompute_kernel — wait before first read.
    asm volatile("griddepcontrol.wait;" ::: "memory");

    float acc = 0.0f;
    for (int t = tid; t < total; t += NTHREADS) {
        const int i = t / nq;
        const int j = t - i * nq;
        const int c = ec[i];
        const int q = qp[j];
        const int sq = qsg[j];

        ulonglong2 m = g_pack[c * C + q];
        int k;
        if (sq > 0) k = __popcll(m.x & negLo) + __popcll(m.y & negHi);
        else        k = __popcll(m.x & posLo) + __popcll(m.y & posHi);

        float base = __uint_as_float((unsigned)(m.y >> 32));
        // exp(k * log(0.5)) == 2^-k to ~1e-8 rel; k <= 81 so no underflow
        float w = __int_as_float((unsigned)(127 - k) << 23);
        acc += base * w * (float)sq;
    }

    // block reduction: 16 warps
    #pragma unroll
    for (int o = 16; o > 0; o >>= 1)
        acc += __shfl_down_sync(0xFFFFFFFFu, acc, o);

    __shared__ float wsum[NTHREADS / 32];
    if ((tid & 31) == 0) wsum[tid >> 5] = acc;
    __syncthreads();
    if (tid == 0) {
        float r = 0.0f;
        #pragma unroll
        for (int w = 0; w < NTHREADS / 32; w++) r += wsum[w];
        out[b] = r;
    }
}

extern "C" void kernel_launch(void* const* d_in, const int* in_sizes, int n_in,
                              void* d_out, int out_size) {
    // all_coords: 81x3 int32 (243 elems); board: 81 float32
    int ci = (in_sizes[0] == 3 * C) ? 0 : 1;
    int bi = 1 - ci;
    const int*   all_coords = (const int*)d_in[ci];
    const float* board      = (const float*)d_in[bi];
    float*       out        = (float*)d_out;

    precompute_kernel<<<C, 128>>>(all_coords);

    // Launch influence with Programmatic Dependent Launch so its prologue
    // (board load, list/mask build) overlaps precompute's execution.
    cudaLaunchConfig_t cfg = {};
    cfg.gridDim  = dim3(C);
    cfg.blockDim = dim3(NTHREADS);
    cfg.dynamicSmemBytes = 0;
    cfg.stream = 0;
    cudaLaunchAttribute attrs[1];
    attrs[0].id = cudaLaunchAttributeProgrammaticStreamSerialization;
    attrs[0].val.programmaticStreamSerializationAllowed = 1;
    cfg.attrs = attrs;
    cfg.numAttrs = 1;
    cudaLaunchKernelEx(&cfg, influence_kernel, board, out);
}